// round 6
// baseline (speedup 1.0000x reference)
#include <cuda_runtime.h>
#include <cuda_bf16.h>
#include <math.h>
#include <stdint.h>

#define D 128
#define NMAX 50000
#define EMAX 800000
#define GMAX 512
#define BN_EPS 1e-5f
#define SLOPE 0.1f
#define SROWS 256
#define SPMAX 256

// ---------------- scratch (static device globals; no allocation) -------------
__device__ float    g_buf1[NMAX * D];
__device__ float    g_buf2[NMAX * D];
__device__ uint32_t g_WBh[3][D * 64];   // packed bf16 pairs of W^T (hi)
__device__ uint32_t g_WBl[3][D * 64];   // packed bf16 pairs (lo residual)
__device__ float    g_dinv[NMAX];
__device__ int      g_deg[NMAX];
__device__ int      g_rowstart[NMAX + 1];
__device__ int      g_wpos[NMAX];
__device__ int      g_srcs[EMAX];
__device__ float    g_ecoef[EMAX];
__device__ float    g_psum[SPMAX * D];
__device__ float    g_psumsq[SPMAX * D];
__device__ float    g_scale[D];
__device__ float    g_shift[D];
__device__ int      g_gcnt[GMAX];
__device__ int      g_gstart[GMAX + 1];
__device__ float    g_pooled[GMAX * D];
__device__ float    g_z1[GMAX * D];
__device__ float    g_z2[GMAX * D];
__device__ int      g_stats_cnt = 0;

// ---------------- bf16 split helpers -----------------------------------------
__device__ __forceinline__ void bf16_split_pack(float v0, float v1,
                                                uint32_t& h, uint32_t& l) {
    __nv_bfloat16 h0 = __float2bfloat16_rn(v0);
    __nv_bfloat16 h1 = __float2bfloat16_rn(v1);
    float r0 = v0 - __bfloat162float(h0);
    float r1 = v1 - __bfloat162float(h1);
    __nv_bfloat16 l0 = __float2bfloat16_rn(r0);
    __nv_bfloat16 l1 = __float2bfloat16_rn(r1);
    h = ((uint32_t)__bfloat16_as_ushort(h1) << 16) | __bfloat16_as_ushort(h0);
    l = ((uint32_t)__bfloat16_as_ushort(l1) << 16) | __bfloat16_as_ushort(l0);
}

__device__ __forceinline__ void mma_bf16(float* d, const uint32_t* a, const uint32_t* b) {
    asm volatile(
        "mma.sync.aligned.m16n8k16.row.col.f32.bf16.bf16.f32 "
        "{%0,%1,%2,%3}, {%4,%5,%6,%7}, {%8,%9}, {%0,%1,%2,%3};"
        : "+f"(d[0]), "+f"(d[1]), "+f"(d[2]), "+f"(d[3])
        : "r"(a[0]), "r"(a[1]), "r"(a[2]), "r"(a[3]), "r"(b[0]), "r"(b[1]));
}

// ---------------- bf16 3-term split GEMM --------------------------------------
// C[M,128] = leaky(norm(A)) @ W ;  B given as packed bf16-pair WT[n][k] hi/lo
#define ASTU 36                       // uint32 row stride, A pair tiles
#define BSTU 68                       // uint32 row stride, B pair tiles
#define SA_H 0
#define SA_L (128 * ASTU)             // 4608
#define SB_H (2 * 128 * ASTU)         // 9216
#define SB_L (SB_H + 128 * BSTU)      // 17920
#define GEMM_U32 (SB_H + 2 * 128 * BSTU)  // 26624 u32 = 106496 B

__global__ void __launch_bounds__(256, 2)
k_gemm_bf16(const float* __restrict__ A, const uint32_t* __restrict__ Bh,
            const uint32_t* __restrict__ Bl, float* __restrict__ C,
            int M, int apply_norm) {
    extern __shared__ uint32_t su[];
    uint32_t* sAh = su + SA_H;
    uint32_t* sAl = su + SA_L;
    uint32_t* sBh = su + SB_H;
    uint32_t* sBl = su + SB_L;

    const int tid = threadIdx.x;
    const int wid = tid >> 5;
    const int lid = tid & 31;
    const int g   = lid >> 2;
    const int tg  = lid & 3;
    const int wm  = wid & 1;       // 2 warp-rows x 64
    const int wn  = wid >> 1;      // 4 warp-cols x 32
    const int row0 = blockIdx.x * 128;

    // load whole B (hi+lo) once: 128 rows x 64 pairs each
#pragma unroll
    for (int i = 0; i < 8; i++) {
        int idx = tid + i * 256;             // 0..2047
        int r = idx >> 4;
        int q = (idx & 15) * 4;
        *(uint4*)&sBh[r * BSTU + q] = *(const uint4*)&Bh[r * 64 + q];
        *(uint4*)&sBl[r * BSTU + q] = *(const uint4*)&Bl[r * 64 + q];
    }

    float acc[4][4][4];
#pragma unroll
    for (int mt = 0; mt < 4; mt++)
#pragma unroll
        for (int nt = 0; nt < 4; nt++)
#pragma unroll
            for (int i = 0; i < 4; i++) acc[mt][nt][i] = 0.0f;

    for (int p = 0; p < 2; p++) {
        if (p) __syncthreads();
        // load + norm + split A chunk [128 x 64]
#pragma unroll
        for (int i = 0; i < 8; i++) {
            int idx = tid + i * 256;
            int r = idx >> 4;
            int c4 = (idx & 15) * 4;
            float4 v = make_float4(0.f, 0.f, 0.f, 0.f);
            if (row0 + r < M)
                v = *(const float4*)&A[(size_t)(row0 + r) * 128 + p * 64 + c4];
            if (apply_norm) {
                int cg = p * 64 + c4;
                v.x = v.x * g_scale[cg]     + g_shift[cg];
                v.y = v.y * g_scale[cg + 1] + g_shift[cg + 1];
                v.z = v.z * g_scale[cg + 2] + g_shift[cg + 2];
                v.w = v.w * g_scale[cg + 3] + g_shift[cg + 3];
                v.x = v.x > 0.f ? v.x : SLOPE * v.x;
                v.y = v.y > 0.f ? v.y : SLOPE * v.y;
                v.z = v.z > 0.f ? v.z : SLOPE * v.z;
                v.w = v.w > 0.f ? v.w : SLOPE * v.w;
            }
            uint2 hp, lp;
            bf16_split_pack(v.x, v.y, hp.x, lp.x);
            bf16_split_pack(v.z, v.w, hp.y, lp.y);
            *(uint2*)&sAh[r * ASTU + (c4 >> 1)] = hp;
            *(uint2*)&sAl[r * ASTU + (c4 >> 1)] = lp;
        }
        __syncthreads();

#pragma unroll
        for (int k16 = 0; k16 < 4; k16++) {
            int kb = k16 * 8;
            uint32_t af[4][4], bh[4][2], bl[4][2];
#pragma unroll
            for (int mt = 0; mt < 4; mt++) {
                int r0 = (wm * 64 + mt * 16 + g) * ASTU + kb + tg;
                af[mt][0] = sAh[r0];
                af[mt][1] = sAh[r0 + 8 * ASTU];
                af[mt][2] = sAh[r0 + 4];
                af[mt][3] = sAh[r0 + 8 * ASTU + 4];
            }
#pragma unroll
            for (int nt = 0; nt < 4; nt++) {
                int rb = (wn * 32 + nt * 8 + g) * BSTU + p * 32 + kb + tg;
                bh[nt][0] = sBh[rb]; bh[nt][1] = sBh[rb + 4];
                bl[nt][0] = sBl[rb]; bl[nt][1] = sBl[rb + 4];
            }
#pragma unroll
            for (int mt = 0; mt < 4; mt++)
#pragma unroll
                for (int nt = 0; nt < 4; nt++)
                    mma_bf16(acc[mt][nt], af[mt], bh[nt]);
#pragma unroll
            for (int mt = 0; mt < 4; mt++)
#pragma unroll
                for (int nt = 0; nt < 4; nt++)
                    mma_bf16(acc[mt][nt], af[mt], bl[nt]);
#pragma unroll
            for (int mt = 0; mt < 4; mt++) {
                int r0 = (wm * 64 + mt * 16 + g) * ASTU + kb + tg;
                af[mt][0] = sAl[r0];
                af[mt][1] = sAl[r0 + 8 * ASTU];
                af[mt][2] = sAl[r0 + 4];
                af[mt][3] = sAl[r0 + 8 * ASTU + 4];
            }
#pragma unroll
            for (int mt = 0; mt < 4; mt++)
#pragma unroll
                for (int nt = 0; nt < 4; nt++)
                    mma_bf16(acc[mt][nt], af[mt], bh[nt]);
        }
    }
    __syncthreads();

    // stage through smem for coalesced stores
    float* sOut = (float*)su;          // 128 x 129 floats, scalar access only
#pragma unroll
    for (int mt = 0; mt < 4; mt++) {
        int r0 = wm * 64 + mt * 16 + g;
#pragma unroll
        for (int nt = 0; nt < 4; nt++) {
            int c0 = wn * 32 + nt * 8 + tg * 2;
            sOut[r0 * 129 + c0]           = acc[mt][nt][0];
            sOut[r0 * 129 + c0 + 1]       = acc[mt][nt][1];
            sOut[(r0 + 8) * 129 + c0]     = acc[mt][nt][2];
            sOut[(r0 + 8) * 129 + c0 + 1] = acc[mt][nt][3];
        }
    }
    __syncthreads();

#pragma unroll 4
    for (int i = 0; i < 64; i++) {
        int idx = tid + i * 256;
        int r = idx >> 7;
        int c = idx & 127;
        if (row0 + r < M)
            C[(size_t)(row0 + r) * 128 + c] = sOut[r * 129 + c];
    }
}

// ---------------- weight prep: transpose + bf16 split + pack -----------------
__global__ void k_prep(const float* __restrict__ W1, const float* __restrict__ W2,
                       const float* __restrict__ W3) {
    __shared__ float s[32][33];
    const float* W = (blockIdx.z == 0) ? W1 : (blockIdx.z == 1) ? W2 : W3;
    uint32_t* Oh = g_WBh[blockIdx.z];
    uint32_t* Ol = g_WBl[blockIdx.z];
    int bx = blockIdx.x, by = blockIdx.y;
    int tx = threadIdx.x, ty = threadIdx.y;
#pragma unroll
    for (int i = 0; i < 32; i += 8)
        s[ty + i][tx] = W[(by * 32 + ty + i) * 128 + bx * 32 + tx];
    __syncthreads();
    // WT[n][k] = W[k][n]; n = bx*32+tx, k = by*32 + (2p, 2p+1)
#pragma unroll
    for (int p = ty; p < 16; p += 8) {
        float v0 = s[2 * p][tx];
        float v1 = s[2 * p + 1][tx];
        uint32_t h, l;
        bf16_split_pack(v0, v1, h, l);
        int o = (bx * 32 + tx) * 64 + by * 16 + p;
        Oh[o] = h;
        Ol[o] = l;
    }
}

// ---------------- init / count -----------------------------------------------
__global__ void k_zero(int N) {
    int i = blockIdx.x * blockDim.x + threadIdx.x;
    if (i < N) g_deg[i] = 0;
    if (i < GMAX) g_gcnt[i] = 0;
    if (i == 0) g_stats_cnt = 0;
}
__global__ void k_count(const int* __restrict__ ei, const int* __restrict__ batch,
                        int E, int N) {
    int i = blockIdx.x * blockDim.x + threadIdx.x;
    if (i < E) atomicAdd(&g_deg[ei[E + i]], 1);
    if (i < N) atomicAdd(&g_gcnt[batch[i]], 1);
}

// ---------------- single-block scan: rowstart + dinv + gstart ----------------
__global__ void k_scan_all(int N, int G) {
    __shared__ int s[1024];
    int t = threadIdx.x;
    int chunk = (N + 1023) / 1024;
    int beg = min(N, t * chunk);
    int end = min(N, beg + chunk);
    int sum = 0;
    for (int i = beg; i < end; i++) {
        int d = g_deg[i];
        sum += d;
        g_dinv[i] = rsqrtf((float)d + 1.0f);
    }
    s[t] = sum;
    __syncthreads();
    for (int off = 1; off < 1024; off <<= 1) {
        int v = (t >= off) ? s[t - off] : 0;
        __syncthreads();
        s[t] += v;
        __syncthreads();
    }
    int run = s[t] - sum;
    for (int i = beg; i < end; i++) {
        g_rowstart[i] = run;
        g_wpos[i] = run;
        run += g_deg[i];
    }
    if (t == 1023) g_rowstart[N] = run;
    __syncthreads();
    // graph ranges
    int gc = (t < G) ? g_gcnt[t] : 0;
    s[t] = gc;
    __syncthreads();
    for (int off = 1; off < 1024; off <<= 1) {
        int v = (t >= off) ? s[t - off] : 0;
        __syncthreads();
        s[t] += v;
        __syncthreads();
    }
    if (t < G) g_gstart[t] = s[t] - gc;
    if (t == G - 1) g_gstart[G] = s[t];
}

__global__ void k_scatter(const int* __restrict__ ei, int E) {
    int e = blockIdx.x * blockDim.x + threadIdx.x;
    if (e < E) {
        int s = ei[e];
        int d = ei[E + e];
        int p = atomicAdd(&g_wpos[d], 1);
        g_srcs[p] = s;
        g_ecoef[p] = g_dinv[s] * g_dinv[d];
    }
}

// ---------------- edge aggregation: warp/dst, 4-wide MLP ---------------------
__global__ void k_aggregate(const float* __restrict__ h, const float* __restrict__ bias,
                            float* __restrict__ agg, int N) {
    int warp = (blockIdx.x * blockDim.x + threadIdx.x) >> 5;
    int lane = threadIdx.x & 31;
    if (warp >= N) return;
    const float4* __restrict__ h4 = (const float4*)h;
    float di = g_dinv[warp];
    float sc = di * di;
    float4 a = h4[(size_t)warp * 32 + lane];
    float4 acc0, acc1, acc2, acc3;
    acc0.x = a.x * sc; acc0.y = a.y * sc; acc0.z = a.z * sc; acc0.w = a.w * sc;
    acc1 = make_float4(0.f, 0.f, 0.f, 0.f);
    acc2 = make_float4(0.f, 0.f, 0.f, 0.f);
    acc3 = make_float4(0.f, 0.f, 0.f, 0.f);

    int j = g_rowstart[warp];
    int s1 = g_rowstart[warp + 1];
    for (; j + 4 <= s1; j += 4) {
        int i0 = g_srcs[j], i1 = g_srcs[j + 1], i2 = g_srcs[j + 2], i3 = g_srcs[j + 3];
        float c0 = g_ecoef[j], c1 = g_ecoef[j + 1], c2 = g_ecoef[j + 2], c3 = g_ecoef[j + 3];
        float4 v0 = h4[(size_t)i0 * 32 + lane];
        float4 v1 = h4[(size_t)i1 * 32 + lane];
        float4 v2 = h4[(size_t)i2 * 32 + lane];
        float4 v3 = h4[(size_t)i3 * 32 + lane];
        acc0.x += v0.x * c0; acc0.y += v0.y * c0; acc0.z += v0.z * c0; acc0.w += v0.w * c0;
        acc1.x += v1.x * c1; acc1.y += v1.y * c1; acc1.z += v1.z * c1; acc1.w += v1.w * c1;
        acc2.x += v2.x * c2; acc2.y += v2.y * c2; acc2.z += v2.z * c2; acc2.w += v2.w * c2;
        acc3.x += v3.x * c3; acc3.y += v3.y * c3; acc3.z += v3.z * c3; acc3.w += v3.w * c3;
    }
    for (; j < s1; j++) {
        int s = g_srcs[j];
        float c = g_ecoef[j];
        float4 v = h4[(size_t)s * 32 + lane];
        acc0.x += v.x * c; acc0.y += v.y * c; acc0.z += v.z * c; acc0.w += v.w * c;
    }
    float4 b = ((const float4*)bias)[lane];
    acc0.x += acc1.x + acc2.x + acc3.x + b.x;
    acc0.y += acc1.y + acc2.y + acc3.y + b.y;
    acc0.z += acc1.z + acc2.z + acc3.z + b.z;
    acc0.w += acc1.w + acc2.w + acc3.w + b.w;
    ((float4*)agg)[(size_t)warp * 32 + lane] = acc0;
}

// ---------------- fused BatchNorm stats (partial + last-block final) ---------
__global__ void k_stats(const float* __restrict__ X, int N, int P,
                        const float* __restrict__ g, const float* __restrict__ be) {
    __shared__ int s_ticket;
    int c = threadIdx.x;
    int r0 = blockIdx.x * SROWS;
    int r1 = min(N, r0 + SROWS);
    float s = 0.f, s2 = 0.f;
    for (int r = r0; r < r1; r++) {
        float v = X[(size_t)r * 128 + c];
        s += v; s2 += v * v;
    }
    g_psum[blockIdx.x * 128 + c] = s;
    g_psumsq[blockIdx.x * 128 + c] = s2;
    __threadfence();
    if (c == 0) s_ticket = atomicAdd(&g_stats_cnt, 1);
    __syncthreads();
    if (s_ticket == P - 1) {
        float ts = 0.f, ts2 = 0.f;
        for (int p = 0; p < P; p++) {
            ts += g_psum[p * 128 + c];
            ts2 += g_psumsq[p * 128 + c];
        }
        float mu = ts / (float)N;
        float var = ts2 / (float)N - mu * mu;
        float rinv = rsqrtf(var + BN_EPS);
        float sc = rinv * g[c];
        g_scale[c] = sc;
        g_shift[c] = be[c] - mu * sc;
        if (c == 0) g_stats_cnt = 0;
    }
}

// ---------------- mean pool with fused norm+leaky ----------------------------
__global__ void k_pool(const float* __restrict__ h, int G) {
    int warp = (blockIdx.x * blockDim.x + threadIdx.x) >> 5;
    int lane = threadIdx.x & 31;
    if (warp >= G) return;
    const float4* h4 = (const float4*)h;
    int c = lane * 4;
    float4 sc = make_float4(g_scale[c], g_scale[c + 1], g_scale[c + 2], g_scale[c + 3]);
    float4 sh = make_float4(g_shift[c], g_shift[c + 1], g_shift[c + 2], g_shift[c + 3]);
    int s0 = g_gstart[warp], s1 = g_gstart[warp + 1];
    float4 acc = make_float4(0.f, 0.f, 0.f, 0.f);
    for (int r = s0; r < s1; r++) {
        float4 v = h4[(size_t)r * 32 + lane];
        float tx = v.x * sc.x + sh.x;
        float ty = v.y * sc.y + sh.y;
        float tz = v.z * sc.z + sh.z;
        float tw = v.w * sc.w + sh.w;
        acc.x += tx > 0.f ? tx : SLOPE * tx;
        acc.y += ty > 0.f ? ty : SLOPE * ty;
        acc.z += tz > 0.f ? tz : SLOPE * tz;
        acc.w += tw > 0.f ? tw : SLOPE * tw;
    }
    int cnt = s1 - s0;
    float inv = 1.0f / (float)(cnt > 0 ? cnt : 1);
    acc.x *= inv; acc.y *= inv; acc.z *= inv; acc.w *= inv;
    ((float4*)g_pooled)[(size_t)warp * 32 + lane] = acc;
}

// ---------------- small-M SIMT GEMM (tail FC layers), 32-row tiles -----------
__global__ void k_gemm_small(const float* __restrict__ A, const float* __restrict__ B,
                             const float* __restrict__ bias, float* __restrict__ C,
                             int M) {
    __shared__ float As[32][36];
    __shared__ float Bs[32][132];   // stride divisible by 4 -> aligned float4
    const int tid = threadIdx.x;
    const int tx = tid & 31;
    const int ty = tid >> 5;
    const int row0 = blockIdx.x * 32;

    float acc[4][4];
#pragma unroll
    for (int i = 0; i < 4; i++)
#pragma unroll
        for (int j = 0; j < 4; j++) acc[i][j] = 0.0f;

    for (int k0 = 0; k0 < 128; k0 += 32) {
        if (k0) __syncthreads();
        {
            int r = tid >> 3, c = (tid & 7) * 4;
            float4 v = make_float4(0.f, 0.f, 0.f, 0.f);
            if (row0 + r < M)
                v = *(const float4*)&A[(size_t)(row0 + r) * 128 + k0 + c];
            As[r][c] = v.x; As[r][c + 1] = v.y; As[r][c + 2] = v.z; As[r][c + 3] = v.w;
        }
#pragma unroll
        for (int i = 0; i < 4; i++) {
            int idx = tid + i * 256;
            int r = idx >> 5, c = (idx & 31) * 4;
            float4 v = *(const float4*)&B[(size_t)(k0 + r) * 128 + c];
            *(float4*)&Bs[r][c] = v;
        }
        __syncthreads();
#pragma unroll
        for (int k = 0; k < 32; k++) {
            float a[4];
#pragma unroll
            for (int i = 0; i < 4; i++) a[i] = As[ty * 4 + i][k];
            float4 b = *(const float4*)&Bs[k][tx * 4];
#pragma unroll
            for (int i = 0; i < 4; i++) {
                acc[i][0] += a[i] * b.x;
                acc[i][1] += a[i] * b.y;
                acc[i][2] += a[i] * b.z;
                acc[i][3] += a[i] * b.w;
            }
        }
    }
    float bx = bias[tx * 4], by = bias[tx * 4 + 1], bz = bias[tx * 4 + 2], bw = bias[tx * 4 + 3];
#pragma unroll
    for (int i = 0; i < 4; i++) {
        int r = row0 + ty * 4 + i;
        if (r < M) {
            float4 o;
            o.x = acc[i][0] + bx;
            o.y = acc[i][1] + by;
            o.z = acc[i][2] + bz;
            o.w = acc[i][3] + bw;
            *(float4*)&C[(size_t)r * 128 + tx * 4] = o;
        }
    }
}

// ---------------- small BN + leaky over G rows -------------------------------
__global__ void k_bn_small(const float* __restrict__ z, const float* __restrict__ g4,
                           const float* __restrict__ be4, float* __restrict__ out, int G) {
    int c = threadIdx.x;
    float s = 0.f, s2 = 0.f;
    for (int r = 0; r < G; r++) {
        float v = z[(size_t)r * 128 + c];
        s += v; s2 += v * v;
    }
    float mu = s / (float)G;
    float var = s2 / (float)G - mu * mu;
    float rinv = rsqrtf(var + BN_EPS);
    float gg = g4[c], bb = be4[c];
    for (int r = 0; r < G; r++) {
        float v = z[(size_t)r * 128 + c];
        float t = (v - mu) * rinv * gg + bb;
        out[(size_t)r * 128 + c] = t > 0.f ? t : SLOPE * t;
    }
}

// ---------------- driver ------------------------------------------------------
extern "C" void kernel_launch(void* const* d_in, const int* in_sizes, int n_in,
                              void* d_out, int out_size) {
    const float* x      = (const float*)d_in[0];
    const int*   ei     = (const int*)d_in[1];
    const int*   batch  = (const int*)d_in[2];
    const float* W1  = (const float*)d_in[4];
    const float* b1  = (const float*)d_in[5];
    const float* g1  = (const float*)d_in[6];
    const float* be1 = (const float*)d_in[7];
    const float* W2  = (const float*)d_in[8];
    const float* b2  = (const float*)d_in[9];
    const float* g2  = (const float*)d_in[10];
    const float* be2 = (const float*)d_in[11];
    const float* W3  = (const float*)d_in[12];
    const float* b3  = (const float*)d_in[13];
    const float* g3  = (const float*)d_in[14];
    const float* be3 = (const float*)d_in[15];
    const float* Wf1 = (const float*)d_in[16];
    const float* bf1 = (const float*)d_in[17];
    const float* g4  = (const float*)d_in[18];
    const float* be4 = (const float*)d_in[19];
    const float* Wf2 = (const float*)d_in[20];
    const float* bf2 = (const float*)d_in[21];

    int N = in_sizes[0] / D;
    int E = in_sizes[1] / 2;
    int G = out_size / D;
    if (N > NMAX || E > EMAX || G > GMAX) return;

    cudaFuncSetAttribute(k_gemm_bf16, cudaFuncAttributeMaxDynamicSharedMemorySize,
                         GEMM_U32 * 4);

    float *buf1, *buf2, *pooled, *z1, *z2;
    uint32_t *wbh, *wbl;
    cudaGetSymbolAddress((void**)&buf1, g_buf1);
    cudaGetSymbolAddress((void**)&buf2, g_buf2);
    cudaGetSymbolAddress((void**)&pooled, g_pooled);
    cudaGetSymbolAddress((void**)&z1, g_z1);
    cudaGetSymbolAddress((void**)&z2, g_z2);
    cudaGetSymbolAddress((void**)&wbh, g_WBh);
    cudaGetSymbolAddress((void**)&wbl, g_WBl);

    int P  = (N + SROWS - 1) / SROWS;
    int mx = max(E, N);

    k_prep<<<dim3(4, 4, 3), dim3(32, 8)>>>(W1, W2, W3);
    k_zero<<<(N + 255) / 256, 256>>>(N);
    k_count<<<(mx + 255) / 256, 256>>>(ei, batch, E, N);
    k_scan_all<<<1, 1024>>>(N, G);
    k_scatter<<<(E + 255) / 256, 256>>>(ei, E);

    const float* bs[3]  = {b1, b2, b3};
    const float* gs[3]  = {g1, g2, g3};
    const float* bes[3] = {be1, be2, be3};

    int tc_grid    = (N + 127) / 128;
    int agg_blocks = (N + 7) / 8;

    const float* xin = x;
    for (int L = 0; L < 3; L++) {
        k_gemm_bf16<<<tc_grid, 256, GEMM_U32 * 4>>>(xin, wbh + L * D * 64,
                                                    wbl + L * D * 64, buf1, N, L > 0);
        k_aggregate<<<agg_blocks, 256>>>(buf1, bs[L], buf2, N);
        k_stats<<<P, 128>>>(buf2, N, P, gs[L], bes[L]);
        xin = buf2;
    }

    // pool applies final norm+leaky inline
    k_pool<<<(G + 7) / 8, 256>>>(buf2, G);
    int sg = (G + 31) / 32;
    k_gemm_small<<<sg, 256>>>(pooled, Wf1, bf1, z1, G);
    k_bn_small<<<1, 128>>>(z1, g4, be4, z2, G);
    k_gemm_small<<<sg, 256>>>(z2, Wf2, bf2, (float*)d_out, G);
}

// round 7
// speedup vs baseline: 1.2846x; 1.2846x over previous
#include <cuda_runtime.h>
#include <cuda_bf16.h>
#include <math.h>
#include <stdint.h>

#define D 128
#define NMAX 50000
#define EMAX 800000
#define GMAX 512
#define BN_EPS 1e-5f
#define SLOPE 0.1f
#define SROWS 256
#define SPMAX 256
#define CH 512
#define NCMAX 512

// ---------------- scratch (static device globals; no allocation) -------------
__device__ float    g_buf1[NMAX * D];
__device__ float    g_buf2[NMAX * D];
__device__ uint32_t g_WBh[3][D * 64];   // packed bf16 pairs of W^T (hi)
__device__ uint32_t g_WBl[3][D * 64];   // packed bf16 pairs (lo residual)
__device__ float    g_dinv[NMAX];
__device__ int      g_deg[NMAX];
__device__ int      g_rowstart[NMAX + 1];
__device__ int      g_wpos[NMAX];
__device__ int      g_srcs[EMAX];
__device__ float    g_ecoef[EMAX];
__device__ int      g_csum[NCMAX];
__device__ int      g_coff[NCMAX];
__device__ float    g_psum[SPMAX * D];
__device__ float    g_psumsq[SPMAX * D];
__device__ float    g_scale[D];
__device__ float    g_shift[D];
__device__ int      g_gcnt[GMAX];
__device__ int      g_gstart[GMAX + 1];
__device__ float    g_pooled[GMAX * D];
__device__ float    g_z1[GMAX * D];
__device__ float    g_z2[GMAX * D];
__device__ int      g_stats_cnt = 0;
__device__ int      g_scan_cnt = 0;

// ---------------- bf16 split helpers -----------------------------------------
__device__ __forceinline__ void bf16_split_pack(float v0, float v1,
                                                uint32_t& h, uint32_t& l) {
    __nv_bfloat16 h0 = __float2bfloat16_rn(v0);
    __nv_bfloat16 h1 = __float2bfloat16_rn(v1);
    float r0 = v0 - __bfloat162float(h0);
    float r1 = v1 - __bfloat162float(h1);
    __nv_bfloat16 l0 = __float2bfloat16_rn(r0);
    __nv_bfloat16 l1 = __float2bfloat16_rn(r1);
    h = ((uint32_t)__bfloat16_as_ushort(h1) << 16) | __bfloat16_as_ushort(h0);
    l = ((uint32_t)__bfloat16_as_ushort(l1) << 16) | __bfloat16_as_ushort(l0);
}

__device__ __forceinline__ void mma_bf16(float* d, const uint32_t* a, const uint32_t* b) {
    asm volatile(
        "mma.sync.aligned.m16n8k16.row.col.f32.bf16.bf16.f32 "
        "{%0,%1,%2,%3}, {%4,%5,%6,%7}, {%8,%9}, {%0,%1,%2,%3};"
        : "+f"(d[0]), "+f"(d[1]), "+f"(d[2]), "+f"(d[3])
        : "r"(a[0]), "r"(a[1]), "r"(a[2]), "r"(a[3]), "r"(b[0]), "r"(b[1]));
}

// ---------------- bf16 3-term split GEMM --------------------------------------
#define ASTU 36
#define BSTU 68
#define SA_H 0
#define SA_L (128 * ASTU)
#define SB_H (2 * 128 * ASTU)
#define SB_L (SB_H + 128 * BSTU)
#define GEMM_U32 (SB_H + 2 * 128 * BSTU)

__global__ void __launch_bounds__(256, 2)
k_gemm_bf16(const float* __restrict__ A, const uint32_t* __restrict__ Bh,
            const uint32_t* __restrict__ Bl, float* __restrict__ C,
            int M, int apply_norm) {
    extern __shared__ uint32_t su[];
    uint32_t* sAh = su + SA_H;
    uint32_t* sAl = su + SA_L;
    uint32_t* sBh = su + SB_H;
    uint32_t* sBl = su + SB_L;

    const int tid = threadIdx.x;
    const int wid = tid >> 5;
    const int lid = tid & 31;
    const int g   = lid >> 2;
    const int tg  = lid & 3;
    const int wm  = wid & 1;
    const int wn  = wid >> 1;
    const int row0 = blockIdx.x * 128;

#pragma unroll
    for (int i = 0; i < 8; i++) {
        int idx = tid + i * 256;
        int r = idx >> 4;
        int q = (idx & 15) * 4;
        *(uint4*)&sBh[r * BSTU + q] = *(const uint4*)&Bh[r * 64 + q];
        *(uint4*)&sBl[r * BSTU + q] = *(const uint4*)&Bl[r * 64 + q];
    }

    float acc[4][4][4];
#pragma unroll
    for (int mt = 0; mt < 4; mt++)
#pragma unroll
        for (int nt = 0; nt < 4; nt++)
#pragma unroll
            for (int i = 0; i < 4; i++) acc[mt][nt][i] = 0.0f;

    for (int p = 0; p < 2; p++) {
        if (p) __syncthreads();
#pragma unroll
        for (int i = 0; i < 8; i++) {
            int idx = tid + i * 256;
            int r = idx >> 4;
            int c4 = (idx & 15) * 4;
            float4 v = make_float4(0.f, 0.f, 0.f, 0.f);
            if (row0 + r < M)
                v = *(const float4*)&A[(size_t)(row0 + r) * 128 + p * 64 + c4];
            if (apply_norm) {
                int cg = p * 64 + c4;
                v.x = v.x * g_scale[cg]     + g_shift[cg];
                v.y = v.y * g_scale[cg + 1] + g_shift[cg + 1];
                v.z = v.z * g_scale[cg + 2] + g_shift[cg + 2];
                v.w = v.w * g_scale[cg + 3] + g_shift[cg + 3];
                v.x = v.x > 0.f ? v.x : SLOPE * v.x;
                v.y = v.y > 0.f ? v.y : SLOPE * v.y;
                v.z = v.z > 0.f ? v.z : SLOPE * v.z;
                v.w = v.w > 0.f ? v.w : SLOPE * v.w;
            }
            uint2 hp, lp;
            bf16_split_pack(v.x, v.y, hp.x, lp.x);
            bf16_split_pack(v.z, v.w, hp.y, lp.y);
            *(uint2*)&sAh[r * ASTU + (c4 >> 1)] = hp;
            *(uint2*)&sAl[r * ASTU + (c4 >> 1)] = lp;
        }
        __syncthreads();

#pragma unroll
        for (int k16 = 0; k16 < 4; k16++) {
            int kb = k16 * 8;
            uint32_t af[4][4], bh[4][2], bl[4][2];
#pragma unroll
            for (int mt = 0; mt < 4; mt++) {
                int r0 = (wm * 64 + mt * 16 + g) * ASTU + kb + tg;
                af[mt][0] = sAh[r0];
                af[mt][1] = sAh[r0 + 8 * ASTU];
                af[mt][2] = sAh[r0 + 4];
                af[mt][3] = sAh[r0 + 8 * ASTU + 4];
            }
#pragma unroll
            for (int nt = 0; nt < 4; nt++) {
                int rb = (wn * 32 + nt * 8 + g) * BSTU + p * 32 + kb + tg;
                bh[nt][0] = sBh[rb]; bh[nt][1] = sBh[rb + 4];
                bl[nt][0] = sBl[rb]; bl[nt][1] = sBl[rb + 4];
            }
#pragma unroll
            for (int mt = 0; mt < 4; mt++)
#pragma unroll
                for (int nt = 0; nt < 4; nt++)
                    mma_bf16(acc[mt][nt], af[mt], bh[nt]);
#pragma unroll
            for (int mt = 0; mt < 4; mt++)
#pragma unroll
                for (int nt = 0; nt < 4; nt++)
                    mma_bf16(acc[mt][nt], af[mt], bl[nt]);
#pragma unroll
            for (int mt = 0; mt < 4; mt++) {
                int r0 = (wm * 64 + mt * 16 + g) * ASTU + kb + tg;
                af[mt][0] = sAl[r0];
                af[mt][1] = sAl[r0 + 8 * ASTU];
                af[mt][2] = sAl[r0 + 4];
                af[mt][3] = sAl[r0 + 8 * ASTU + 4];
            }
#pragma unroll
            for (int mt = 0; mt < 4; mt++)
#pragma unroll
                for (int nt = 0; nt < 4; nt++)
                    mma_bf16(acc[mt][nt], af[mt], bh[nt]);
        }
    }
    __syncthreads();

    float* sOut = (float*)su;
#pragma unroll
    for (int mt = 0; mt < 4; mt++) {
        int r0 = wm * 64 + mt * 16 + g;
#pragma unroll
        for (int nt = 0; nt < 4; nt++) {
            int c0 = wn * 32 + nt * 8 + tg * 2;
            sOut[r0 * 129 + c0]           = acc[mt][nt][0];
            sOut[r0 * 129 + c0 + 1]       = acc[mt][nt][1];
            sOut[(r0 + 8) * 129 + c0]     = acc[mt][nt][2];
            sOut[(r0 + 8) * 129 + c0 + 1] = acc[mt][nt][3];
        }
    }
    __syncthreads();

#pragma unroll 4
    for (int i = 0; i < 64; i++) {
        int idx = tid + i * 256;
        int r = idx >> 7;
        int c = idx & 127;
        if (row0 + r < M)
            C[(size_t)(row0 + r) * 128 + c] = sOut[r * 129 + c];
    }
}

// ---------------- weight prep: transpose + bf16 split + pack -----------------
__global__ void k_prep(const float* __restrict__ W1, const float* __restrict__ W2,
                       const float* __restrict__ W3) {
    __shared__ float s[32][33];
    const float* W = (blockIdx.z == 0) ? W1 : (blockIdx.z == 1) ? W2 : W3;
    uint32_t* Oh = g_WBh[blockIdx.z];
    uint32_t* Ol = g_WBl[blockIdx.z];
    int bx = blockIdx.x, by = blockIdx.y;
    int tx = threadIdx.x, ty = threadIdx.y;
#pragma unroll
    for (int i = 0; i < 32; i += 8)
        s[ty + i][tx] = W[(by * 32 + ty + i) * 128 + bx * 32 + tx];
    __syncthreads();
#pragma unroll
    for (int p = ty; p < 16; p += 8) {
        float v0 = s[2 * p][tx];
        float v1 = s[2 * p + 1][tx];
        uint32_t h, l;
        bf16_split_pack(v0, v1, h, l);
        int o = (bx * 32 + tx) * 64 + by * 16 + p;
        Oh[o] = h;
        Ol[o] = l;
    }
}

// ---------------- init / count -----------------------------------------------
__global__ void k_zero(int N) {
    int i = blockIdx.x * blockDim.x + threadIdx.x;
    if (i < N) g_deg[i] = 0;
    if (i < GMAX) g_gcnt[i] = 0;
    if (i == 0) { g_stats_cnt = 0; g_scan_cnt = 0; }
}
__global__ void k_count(const int* __restrict__ ei, const int* __restrict__ batch,
                        int E, int N) {
    int i = blockIdx.x * blockDim.x + threadIdx.x;
    if (i < E) atomicAdd(&g_deg[ei[E + i]], 1);
    if (i < N) atomicAdd(&g_gcnt[batch[i]], 1);
}

// ---------------- chunk sums + (last block) chunk-offset & graph scans -------
__global__ void k_chunksum(int N, int NC, int G) {
    __shared__ int s[CH];
    __shared__ int ticket;
    int i = blockIdx.x * CH + threadIdx.x;
    int t = threadIdx.x;
    s[t] = (i < N) ? g_deg[i] : 0;
    __syncthreads();
    for (int off = CH / 2; off > 0; off >>= 1) {
        if (t < off) s[t] += s[t + off];
        __syncthreads();
    }
    if (t == 0) {
        g_csum[blockIdx.x] = s[0];
        __threadfence();
        ticket = atomicAdd(&g_scan_cnt, 1);
    }
    __syncthreads();
    if (ticket == gridDim.x - 1) {
        // scan chunk sums (NC <= 512)
        int cv = (t < NC) ? g_csum[t] : 0;
        s[t] = cv;
        __syncthreads();
        for (int off = 1; off < CH; off <<= 1) {
            int x = (t >= off) ? s[t - off] : 0;
            __syncthreads();
            s[t] += x;
            __syncthreads();
        }
        if (t < NC) g_coff[t] = s[t] - cv;
        if (t == NC - 1) g_rowstart[N] = s[t];
        __syncthreads();
        // graph ranges scan (G <= 512)
        int gc = (t < G) ? g_gcnt[t] : 0;
        s[t] = gc;
        __syncthreads();
        for (int off = 1; off < CH; off <<= 1) {
            int x = (t >= off) ? s[t - off] : 0;
            __syncthreads();
            s[t] += x;
            __syncthreads();
        }
        if (t < G) g_gstart[t] = s[t] - gc;
        if (t == G - 1) g_gstart[G] = s[t];
        if (t == 0) g_scan_cnt = 0;
    }
}

// ---------------- intra-chunk scan -> rowstart/wpos, fused dinv --------------
__global__ void k_chunkscan(int N) {
    __shared__ int s[CH];
    int i = blockIdx.x * CH + threadIdx.x;
    int t = threadIdx.x;
    int v = (i < N) ? g_deg[i] : 0;
    s[t] = v;
    __syncthreads();
    for (int off = 1; off < CH; off <<= 1) {
        int x = (t >= off) ? s[t - off] : 0;
        __syncthreads();
        s[t] += x;
        __syncthreads();
    }
    if (i < N) {
        int excl = g_coff[blockIdx.x] + s[t] - v;
        g_rowstart[i] = excl;
        g_wpos[i] = excl;
        g_dinv[i] = rsqrtf((float)v + 1.0f);
    }
}

__global__ void k_scatter(const int* __restrict__ ei, int E) {
    int e = blockIdx.x * blockDim.x + threadIdx.x;
    if (e < E) {
        int s = ei[e];
        int d = ei[E + e];
        int p = atomicAdd(&g_wpos[d], 1);
        g_srcs[p] = s;
        g_ecoef[p] = g_dinv[s] * g_dinv[d];
    }
}

// ---------------- edge aggregation: warp/dst, 4-wide MLP ---------------------
__global__ void k_aggregate(const float* __restrict__ h, const float* __restrict__ bias,
                            float* __restrict__ agg, int N) {
    int warp = (blockIdx.x * blockDim.x + threadIdx.x) >> 5;
    int lane = threadIdx.x & 31;
    if (warp >= N) return;
    const float4* __restrict__ h4 = (const float4*)h;
    float di = g_dinv[warp];
    float sc = di * di;
    float4 a = h4[(size_t)warp * 32 + lane];
    float4 acc0, acc1, acc2, acc3;
    acc0.x = a.x * sc; acc0.y = a.y * sc; acc0.z = a.z * sc; acc0.w = a.w * sc;
    acc1 = make_float4(0.f, 0.f, 0.f, 0.f);
    acc2 = make_float4(0.f, 0.f, 0.f, 0.f);
    acc3 = make_float4(0.f, 0.f, 0.f, 0.f);

    int j = g_rowstart[warp];
    int s1 = g_rowstart[warp + 1];
    for (; j + 4 <= s1; j += 4) {
        int i0 = g_srcs[j], i1 = g_srcs[j + 1], i2 = g_srcs[j + 2], i3 = g_srcs[j + 3];
        float c0 = g_ecoef[j], c1 = g_ecoef[j + 1], c2 = g_ecoef[j + 2], c3 = g_ecoef[j + 3];
        float4 v0 = h4[(size_t)i0 * 32 + lane];
        float4 v1 = h4[(size_t)i1 * 32 + lane];
        float4 v2 = h4[(size_t)i2 * 32 + lane];
        float4 v3 = h4[(size_t)i3 * 32 + lane];
        acc0.x += v0.x * c0; acc0.y += v0.y * c0; acc0.z += v0.z * c0; acc0.w += v0.w * c0;
        acc1.x += v1.x * c1; acc1.y += v1.y * c1; acc1.z += v1.z * c1; acc1.w += v1.w * c1;
        acc2.x += v2.x * c2; acc2.y += v2.y * c2; acc2.z += v2.z * c2; acc2.w += v2.w * c2;
        acc3.x += v3.x * c3; acc3.y += v3.y * c3; acc3.z += v3.z * c3; acc3.w += v3.w * c3;
    }
    for (; j < s1; j++) {
        int s = g_srcs[j];
        float c = g_ecoef[j];
        float4 v = h4[(size_t)s * 32 + lane];
        acc0.x += v.x * c; acc0.y += v.y * c; acc0.z += v.z * c; acc0.w += v.w * c;
    }
    float4 b = ((const float4*)bias)[lane];
    acc0.x += acc1.x + acc2.x + acc3.x + b.x;
    acc0.y += acc1.y + acc2.y + acc3.y + b.y;
    acc0.z += acc1.z + acc2.z + acc3.z + b.z;
    acc0.w += acc1.w + acc2.w + acc3.w + b.w;
    ((float4*)agg)[(size_t)warp * 32 + lane] = acc0;
}

// ---------------- fused BatchNorm stats (partial + last-block final) ---------
__global__ void k_stats(const float* __restrict__ X, int N, int P,
                        const float* __restrict__ g, const float* __restrict__ be) {
    __shared__ int s_ticket;
    int c = threadIdx.x;
    int r0 = blockIdx.x * SROWS;
    int r1 = min(N, r0 + SROWS);
    float s = 0.f, s2 = 0.f;
    for (int r = r0; r < r1; r++) {
        float v = X[(size_t)r * 128 + c];
        s += v; s2 += v * v;
    }
    g_psum[blockIdx.x * 128 + c] = s;
    g_psumsq[blockIdx.x * 128 + c] = s2;
    __threadfence();
    if (c == 0) s_ticket = atomicAdd(&g_stats_cnt, 1);
    __syncthreads();
    if (s_ticket == P - 1) {
        float ts = 0.f, ts2 = 0.f;
        for (int p = 0; p < P; p++) {
            ts += g_psum[p * 128 + c];
            ts2 += g_psumsq[p * 128 + c];
        }
        float mu = ts / (float)N;
        float var = ts2 / (float)N - mu * mu;
        float rinv = rsqrtf(var + BN_EPS);
        float sc = rinv * g[c];
        g_scale[c] = sc;
        g_shift[c] = be[c] - mu * sc;
        if (c == 0) g_stats_cnt = 0;
    }
}

// ---------------- mean pool with fused norm+leaky ----------------------------
__global__ void k_pool(const float* __restrict__ h, int G) {
    int warp = (blockIdx.x * blockDim.x + threadIdx.x) >> 5;
    int lane = threadIdx.x & 31;
    if (warp >= G) return;
    const float4* h4 = (const float4*)h;
    int c = lane * 4;
    float4 sc = make_float4(g_scale[c], g_scale[c + 1], g_scale[c + 2], g_scale[c + 3]);
    float4 sh = make_float4(g_shift[c], g_shift[c + 1], g_shift[c + 2], g_shift[c + 3]);
    int s0 = g_gstart[warp], s1 = g_gstart[warp + 1];
    float4 acc = make_float4(0.f, 0.f, 0.f, 0.f);
    for (int r = s0; r < s1; r++) {
        float4 v = h4[(size_t)r * 32 + lane];
        float tx = v.x * sc.x + sh.x;
        float ty = v.y * sc.y + sh.y;
        float tz = v.z * sc.z + sh.z;
        float tw = v.w * sc.w + sh.w;
        acc.x += tx > 0.f ? tx : SLOPE * tx;
        acc.y += ty > 0.f ? ty : SLOPE * ty;
        acc.z += tz > 0.f ? tz : SLOPE * tz;
        acc.w += tw > 0.f ? tw : SLOPE * tw;
    }
    int cnt = s1 - s0;
    float inv = 1.0f / (float)(cnt > 0 ? cnt : 1);
    acc.x *= inv; acc.y *= inv; acc.z *= inv; acc.w *= inv;
    ((float4*)g_pooled)[(size_t)warp * 32 + lane] = acc;
}

// ---------------- small-M SIMT GEMM (tail FC layers), 32-row tiles -----------
__global__ void k_gemm_small(const float* __restrict__ A, const float* __restrict__ B,
                             const float* __restrict__ bias, float* __restrict__ C,
                             int M) {
    __shared__ float As[32][36];
    __shared__ float Bs[32][132];
    const int tid = threadIdx.x;
    const int tx = tid & 31;
    const int ty = tid >> 5;
    const int row0 = blockIdx.x * 32;

    float acc[4][4];
#pragma unroll
    for (int i = 0; i < 4; i++)
#pragma unroll
        for (int j = 0; j < 4; j++) acc[i][j] = 0.0f;

    for (int k0 = 0; k0 < 128; k0 += 32) {
        if (k0) __syncthreads();
        {
            int r = tid >> 3, c = (tid & 7) * 4;
            float4 v = make_float4(0.f, 0.f, 0.f, 0.f);
            if (row0 + r < M)
                v = *(const float4*)&A[(size_t)(row0 + r) * 128 + k0 + c];
            As[r][c] = v.x; As[r][c + 1] = v.y; As[r][c + 2] = v.z; As[r][c + 3] = v.w;
        }
#pragma unroll
        for (int i = 0; i < 4; i++) {
            int idx = tid + i * 256;
            int r = idx >> 5, c = (idx & 31) * 4;
            float4 v = *(const float4*)&B[(size_t)(k0 + r) * 128 + c];
            *(float4*)&Bs[r][c] = v;
        }
        __syncthreads();
#pragma unroll
        for (int k = 0; k < 32; k++) {
            float a[4];
#pragma unroll
            for (int i = 0; i < 4; i++) a[i] = As[ty * 4 + i][k];
            float4 b = *(const float4*)&Bs[k][tx * 4];
#pragma unroll
            for (int i = 0; i < 4; i++) {
                acc[i][0] += a[i] * b.x;
                acc[i][1] += a[i] * b.y;
                acc[i][2] += a[i] * b.z;
                acc[i][3] += a[i] * b.w;
            }
        }
    }
    float bx = bias[tx * 4], by = bias[tx * 4 + 1], bz = bias[tx * 4 + 2], bw = bias[tx * 4 + 3];
#pragma unroll
    for (int i = 0; i < 4; i++) {
        int r = row0 + ty * 4 + i;
        if (r < M) {
            float4 o;
            o.x = acc[i][0] + bx;
            o.y = acc[i][1] + by;
            o.z = acc[i][2] + bz;
            o.w = acc[i][3] + bw;
            *(float4*)&C[(size_t)r * 128 + tx * 4] = o;
        }
    }
}

// ---------------- small BN + leaky over G rows -------------------------------
__global__ void k_bn_small(const float* __restrict__ z, const float* __restrict__ g4,
                           const float* __restrict__ be4, float* __restrict__ out, int G) {
    int c = threadIdx.x;
    float s = 0.f, s2 = 0.f;
    for (int r = 0; r < G; r++) {
        float v = z[(size_t)r * 128 + c];
        s += v; s2 += v * v;
    }
    float mu = s / (float)G;
    float var = s2 / (float)G - mu * mu;
    float rinv = rsqrtf(var + BN_EPS);
    float gg = g4[c], bb = be4[c];
    for (int r = 0; r < G; r++) {
        float v = z[(size_t)r * 128 + c];
        float t = (v - mu) * rinv * gg + bb;
        out[(size_t)r * 128 + c] = t > 0.f ? t : SLOPE * t;
    }
}

// ---------------- driver ------------------------------------------------------
extern "C" void kernel_launch(void* const* d_in, const int* in_sizes, int n_in,
                              void* d_out, int out_size) {
    const float* x      = (const float*)d_in[0];
    const int*   ei     = (const int*)d_in[1];
    const int*   batch  = (const int*)d_in[2];
    const float* W1  = (const float*)d_in[4];
    const float* b1  = (const float*)d_in[5];
    const float* g1  = (const float*)d_in[6];
    const float* be1 = (const float*)d_in[7];
    const float* W2  = (const float*)d_in[8];
    const float* b2  = (const float*)d_in[9];
    const float* g2  = (const float*)d_in[10];
    const float* be2 = (const float*)d_in[11];
    const float* W3  = (const float*)d_in[12];
    const float* b3  = (const float*)d_in[13];
    const float* g3  = (const float*)d_in[14];
    const float* be3 = (const float*)d_in[15];
    const float* Wf1 = (const float*)d_in[16];
    const float* bf1 = (const float*)d_in[17];
    const float* g4  = (const float*)d_in[18];
    const float* be4 = (const float*)d_in[19];
    const float* Wf2 = (const float*)d_in[20];
    const float* bf2 = (const float*)d_in[21];

    int N = in_sizes[0] / D;
    int E = in_sizes[1] / 2;
    int G = out_size / D;
    if (N > NMAX || E > EMAX || G > GMAX) return;

    cudaFuncSetAttribute(k_gemm_bf16, cudaFuncAttributeMaxDynamicSharedMemorySize,
                         GEMM_U32 * 4);

    float *buf1, *buf2, *pooled, *z1, *z2;
    uint32_t *wbh, *wbl;
    cudaGetSymbolAddress((void**)&buf1, g_buf1);
    cudaGetSymbolAddress((void**)&buf2, g_buf2);
    cudaGetSymbolAddress((void**)&pooled, g_pooled);
    cudaGetSymbolAddress((void**)&z1, g_z1);
    cudaGetSymbolAddress((void**)&z2, g_z2);
    cudaGetSymbolAddress((void**)&wbh, g_WBh);
    cudaGetSymbolAddress((void**)&wbl, g_WBl);

    int P  = (N + SROWS - 1) / SROWS;
    int NC = (N + CH - 1) / CH;
    int mx = max(E, N);

    k_prep<<<dim3(4, 4, 3), dim3(32, 8)>>>(W1, W2, W3);
    k_zero<<<(N + 255) / 256, 256>>>(N);
    k_count<<<(mx + 255) / 256, 256>>>(ei, batch, E, N);
    k_chunksum<<<NC, CH>>>(N, NC, G);
    k_chunkscan<<<NC, CH>>>(N);
    k_scatter<<<(E + 255) / 256, 256>>>(ei, E);

    const float* bs[3]  = {b1, b2, b3};
    const float* gs[3]  = {g1, g2, g3};
    const float* bes[3] = {be1, be2, be3};

    int tc_grid    = (N + 127) / 128;
    int agg_blocks = (N + 7) / 8;

    const float* xin = x;
    for (int L = 0; L < 3; L++) {
        k_gemm_bf16<<<tc_grid, 256, GEMM_U32 * 4>>>(xin, wbh + L * D * 64,
                                                    wbl + L * D * 64, buf1, N, L > 0);
        k_aggregate<<<agg_blocks, 256>>>(buf1, bs[L], buf2, N);
        k_stats<<<P, 128>>>(buf2, N, P, gs[L], bes[L]);
        xin = buf2;
    }

    // pool applies final norm+leaky inline
    k_pool<<<(G + 7) / 8, 256>>>(buf2, G);
    int sg = (G + 31) / 32;
    k_gemm_small<<<sg, 256>>>(pooled, Wf1, bf1, z1, G);
    k_bn_small<<<1, 128>>>(z1, g4, be4, z2, G);
    k_gemm_small<<<sg, 256>>>(z2, Wf2, bf2, (float*)d_out, G);
}